// round 15
// baseline (speedup 1.0000x reference)
#include <cuda_runtime.h>
#include <cstdint>

// Problem constants (fixed by the reference)
#define DIM      128
#define P_ROWS   50000
#define U_ROWS   100000
#define NNZ_CNT  1600000

// Scratch for the intermediate y = HG_up @ x  : [U, D] fp32 = 51.2 MB
__device__ float g_y[(size_t)U_ROWS * DIM];

// ---------------------------------------------------------------------------
// Kernel 1: zero g_y and initialize out = e - x  (out accumulates phase 2)
// ---------------------------------------------------------------------------
__global__ void init_kernel(const float* __restrict__ x,
                            const float* __restrict__ e,
                            float* __restrict__ out) {
    const int i = blockIdx.x * blockDim.x + threadIdx.x;

    const int ny4 = (U_ROWS * DIM) / 4;     // 3.2M float4
    if (i < ny4) {
        reinterpret_cast<float4*>(g_y)[i] = make_float4(0.f, 0.f, 0.f, 0.f);
    }
    const int no4 = (P_ROWS * DIM) / 4;     // 1.6M float4
    if (i < no4) {
        float4 xv = reinterpret_cast<const float4*>(x)[i];
        float4 ev = reinterpret_cast<const float4*>(e)[i];
        reinterpret_cast<float4*>(out)[i] =
            make_float4(ev.x - xv.x, ev.y - xv.y, ev.z - xv.z, ev.w - xv.w);
    }
}

// ---------------------------------------------------------------------------
// Vectorized global reduction: one 16B RED instead of 4 scalar atomicAdds.
// red.global.add.v4.f32 requires sm_90+; sm_103a supports it.
// ---------------------------------------------------------------------------
__device__ __forceinline__ void red_add_v4(float* addr, float a, float b,
                                           float c, float d) {
    asm volatile("red.global.add.v4.f32 [%0], {%1, %2, %3, %4};"
                 :: "l"(addr), "f"(a), "f"(b), "f"(c), "f"(d)
                 : "memory");
}

// ---------------------------------------------------------------------------
// Warp-per-nnz COO scatter: dst[row] += val * src[col]  (row of D=128 floats)
// Each lane owns one float4 → fully coalesced gather, one v4 RED per lane.
// ---------------------------------------------------------------------------
__device__ __forceinline__ void scatter_row(const float* __restrict__ vals,
                                            const int*   __restrict__ rows,
                                            const int*   __restrict__ cols,
                                            const float* __restrict__ src,
                                            float*       __restrict__ dst,
                                            int nnz) {
    const int gtid = blockIdx.x * blockDim.x + threadIdx.x;
    const int warp = gtid >> 5;
    const int lane = threadIdx.x & 31;
    if (warp >= nnz) return;

    const float v = __ldg(vals + warp);
    const int   r = __ldg(rows + warp);
    const int   c = __ldg(cols + warp);

    const float4 s = reinterpret_cast<const float4*>(src + (size_t)c * DIM)[lane];
    float* d = dst + (size_t)r * DIM + lane * 4;
    red_add_v4(d, v * s.x, v * s.y, v * s.z, v * s.w);
}

// Phase 1: g_y[rows_up] += vals_up * x[cols_up]
__global__ void scatter_phase1(const float* __restrict__ vals,
                               const int*   __restrict__ rows,
                               const int*   __restrict__ cols,
                               const float* __restrict__ x,
                               int nnz) {
    scatter_row(vals, rows, cols, x, g_y, nnz);
}

// Phase 2: out[rows_pu] += vals_pu * g_y[cols_pu]   (out pre-set to e - x)
__global__ void scatter_phase2(const float* __restrict__ vals,
                               const int*   __restrict__ rows,
                               const int*   __restrict__ cols,
                               float*       __restrict__ out,
                               int nnz) {
    scatter_row(vals, rows, cols, g_y, out, nnz);
}

// ---------------------------------------------------------------------------
// Launch
// ---------------------------------------------------------------------------
extern "C" void kernel_launch(void* const* d_in, const int* in_sizes, int n_in,
                              void* d_out, int out_size) {
    // Inputs (metadata order): t, x, e, vals_up, vals_pu,
    //                          rows_up, cols_up, rows_pu, cols_pu
    // Handle a possibly-absent leading scalar 't'.
    const int base = n_in - 8;

    const float* x       = (const float*)d_in[base + 0];
    const float* e       = (const float*)d_in[base + 1];
    const float* vals_up = (const float*)d_in[base + 2];
    const float* vals_pu = (const float*)d_in[base + 3];
    const int*   rows_up = (const int*)  d_in[base + 4];
    const int*   cols_up = (const int*)  d_in[base + 5];
    const int*   rows_pu = (const int*)  d_in[base + 6];
    const int*   cols_pu = (const int*)  d_in[base + 7];

    float* out = (float*)d_out;

    const int threads = 256;

    // init: cover max(y float4 count, out float4 count) = 3.2M threads
    const int ny4 = (U_ROWS * DIM) / 4;
    const int init_blocks = (ny4 + threads - 1) / threads;
    init_kernel<<<init_blocks, threads>>>(x, e, out);

    // scatter: one warp per nnz → NNZ*32 threads
    const long long total_scatter = (long long)NNZ_CNT * 32;
    const int scatter_blocks = (int)((total_scatter + threads - 1) / threads);

    scatter_phase1<<<scatter_blocks, threads>>>(vals_up, rows_up, cols_up, x, NNZ_CNT);
    scatter_phase2<<<scatter_blocks, threads>>>(vals_pu, rows_pu, cols_pu, out, NNZ_CNT);
}

// round 16
// speedup vs baseline: 1.0103x; 1.0103x over previous
#include <cuda_runtime.h>
#include <cstdint>

// Problem constants (fixed by the reference)
#define DIM      128
#define P_ROWS   50000
#define U_ROWS   100000
#define NNZ_CNT  1600000

// Scratch for the intermediate y = HG_up @ x  : [U, D] fp32 = 51.2 MB
__device__ float g_y[(size_t)U_ROWS * DIM];

// ---------------------------------------------------------------------------
// Kernel 1: zero g_y and initialize out = e - x  (out accumulates phase 2)
// ---------------------------------------------------------------------------
__global__ void init_kernel(const float* __restrict__ x,
                            const float* __restrict__ e,
                            float* __restrict__ out) {
    const int i = blockIdx.x * blockDim.x + threadIdx.x;

    const int ny4 = (U_ROWS * DIM) / 4;     // 3.2M float4
    if (i < ny4) {
        reinterpret_cast<float4*>(g_y)[i] = make_float4(0.f, 0.f, 0.f, 0.f);
    }
    const int no4 = (P_ROWS * DIM) / 4;     // 1.6M float4
    if (i < no4) {
        float4 xv = reinterpret_cast<const float4*>(x)[i];
        float4 ev = reinterpret_cast<const float4*>(e)[i];
        reinterpret_cast<float4*>(out)[i] =
            make_float4(ev.x - xv.x, ev.y - xv.y, ev.z - xv.z, ev.w - xv.w);
    }
}

// ---------------------------------------------------------------------------
// Vectorized global reduction: one 16B RED instead of 4 scalar atomicAdds.
// red.global.add.v4.f32 requires sm_90+; sm_103a supports it.
// ---------------------------------------------------------------------------
__device__ __forceinline__ void red_add_v4(float* addr, float a, float b,
                                           float c, float d) {
    asm volatile("red.global.add.v4.f32 [%0], {%1, %2, %3, %4};"
                 :: "l"(addr), "f"(a), "f"(b), "f"(c), "f"(d)
                 : "memory");
}

// ---------------------------------------------------------------------------
// Warp-per-nnz COO scatter: dst[row] += val * src[col]  (row of D=128 floats)
// Each lane owns one float4 → fully coalesced gather, one v4 RED per lane.
// ---------------------------------------------------------------------------
__device__ __forceinline__ void scatter_row(const float* __restrict__ vals,
                                            const int*   __restrict__ rows,
                                            const int*   __restrict__ cols,
                                            const float* __restrict__ src,
                                            float*       __restrict__ dst,
                                            int nnz) {
    const int gtid = blockIdx.x * blockDim.x + threadIdx.x;
    const int warp = gtid >> 5;
    const int lane = threadIdx.x & 31;
    if (warp >= nnz) return;

    const float v = __ldg(vals + warp);
    const int   r = __ldg(rows + warp);
    const int   c = __ldg(cols + warp);

    const float4 s = reinterpret_cast<const float4*>(src + (size_t)c * DIM)[lane];
    float* d = dst + (size_t)r * DIM + lane * 4;
    red_add_v4(d, v * s.x, v * s.y, v * s.z, v * s.w);
}

// Phase 1: g_y[rows_up] += vals_up * x[cols_up]
__global__ void scatter_phase1(const float* __restrict__ vals,
                               const int*   __restrict__ rows,
                               const int*   __restrict__ cols,
                               const float* __restrict__ x,
                               int nnz) {
    scatter_row(vals, rows, cols, x, g_y, nnz);
}

// Phase 2: out[rows_pu] += vals_pu * g_y[cols_pu]   (out pre-set to e - x)
__global__ void scatter_phase2(const float* __restrict__ vals,
                               const int*   __restrict__ rows,
                               const int*   __restrict__ cols,
                               float*       __restrict__ out,
                               int nnz) {
    scatter_row(vals, rows, cols, g_y, out, nnz);
}

// ---------------------------------------------------------------------------
// Launch
// ---------------------------------------------------------------------------
extern "C" void kernel_launch(void* const* d_in, const int* in_sizes, int n_in,
                              void* d_out, int out_size) {
    // Inputs (metadata order): t, x, e, vals_up, vals_pu,
    //                          rows_up, cols_up, rows_pu, cols_pu
    // Handle a possibly-absent leading scalar 't'.
    const int base = n_in - 8;

    const float* x       = (const float*)d_in[base + 0];
    const float* e       = (const float*)d_in[base + 1];
    const float* vals_up = (const float*)d_in[base + 2];
    const float* vals_pu = (const float*)d_in[base + 3];
    const int*   rows_up = (const int*)  d_in[base + 4];
    const int*   cols_up = (const int*)  d_in[base + 5];
    const int*   rows_pu = (const int*)  d_in[base + 6];
    const int*   cols_pu = (const int*)  d_in[base + 7];

    float* out = (float*)d_out;

    const int threads = 256;

    // init: cover max(y float4 count, out float4 count) = 3.2M threads
    const int ny4 = (U_ROWS * DIM) / 4;
    const int init_blocks = (ny4 + threads - 1) / threads;
    init_kernel<<<init_blocks, threads>>>(x, e, out);

    // scatter: one warp per nnz → NNZ*32 threads
    const long long total_scatter = (long long)NNZ_CNT * 32;
    const int scatter_blocks = (int)((total_scatter + threads - 1) / threads);

    scatter_phase1<<<scatter_blocks, threads>>>(vals_up, rows_up, cols_up, x, NNZ_CNT);
    scatter_phase2<<<scatter_blocks, threads>>>(vals_pu, rows_pu, cols_pu, out, NNZ_CNT);
}

// round 17
// speedup vs baseline: 1.0126x; 1.0022x over previous
#include <cuda_runtime.h>
#include <cstdint>

// Problem constants (fixed by the reference)
#define DIM      128
#define P_ROWS   50000
#define U_ROWS   100000
#define NNZ_CNT  1600000

// Scratch for the intermediate y = HG_up @ x  : [U, D] fp32 = 51.2 MB
__device__ float g_y[(size_t)U_ROWS * DIM];

// ---------------------------------------------------------------------------
// Kernel 1: zero g_y and initialize out = e - x  (out accumulates phase 2)
// ---------------------------------------------------------------------------
__global__ void init_kernel(const float* __restrict__ x,
                            const float* __restrict__ e,
                            float* __restrict__ out) {
    const int i = blockIdx.x * blockDim.x + threadIdx.x;

    const int ny4 = (U_ROWS * DIM) / 4;     // 3.2M float4
    if (i < ny4) {
        reinterpret_cast<float4*>(g_y)[i] = make_float4(0.f, 0.f, 0.f, 0.f);
    }
    const int no4 = (P_ROWS * DIM) / 4;     // 1.6M float4
    if (i < no4) {
        float4 xv = reinterpret_cast<const float4*>(x)[i];
        float4 ev = reinterpret_cast<const float4*>(e)[i];
        reinterpret_cast<float4*>(out)[i] =
            make_float4(ev.x - xv.x, ev.y - xv.y, ev.z - xv.z, ev.w - xv.w);
    }
}

// ---------------------------------------------------------------------------
// Vectorized global reduction: one 16B RED instead of 4 scalar atomicAdds.
// red.global.add.v4.f32 requires sm_90+; sm_103a supports it.
// ---------------------------------------------------------------------------
__device__ __forceinline__ void red_add_v4(float* addr, float a, float b,
                                           float c, float d) {
    asm volatile("red.global.add.v4.f32 [%0], {%1, %2, %3, %4};"
                 :: "l"(addr), "f"(a), "f"(b), "f"(c), "f"(d)
                 : "memory");
}

// ---------------------------------------------------------------------------
// Warp-per-nnz COO scatter: dst[row] += val * src[col]  (row of D=128 floats)
// Each lane owns one float4 → fully coalesced gather, one v4 RED per lane.
// ---------------------------------------------------------------------------
__device__ __forceinline__ void scatter_row(const float* __restrict__ vals,
                                            const int*   __restrict__ rows,
                                            const int*   __restrict__ cols,
                                            const float* __restrict__ src,
                                            float*       __restrict__ dst,
                                            int nnz) {
    const int gtid = blockIdx.x * blockDim.x + threadIdx.x;
    const int warp = gtid >> 5;
    const int lane = threadIdx.x & 31;
    if (warp >= nnz) return;

    const float v = __ldg(vals + warp);
    const int   r = __ldg(rows + warp);
    const int   c = __ldg(cols + warp);

    const float4 s = reinterpret_cast<const float4*>(src + (size_t)c * DIM)[lane];
    float* d = dst + (size_t)r * DIM + lane * 4;
    red_add_v4(d, v * s.x, v * s.y, v * s.z, v * s.w);
}

// Phase 1: g_y[rows_up] += vals_up * x[cols_up]
__global__ void scatter_phase1(const float* __restrict__ vals,
                               const int*   __restrict__ rows,
                               const int*   __restrict__ cols,
                               const float* __restrict__ x,
                               int nnz) {
    scatter_row(vals, rows, cols, x, g_y, nnz);
}

// Phase 2: out[rows_pu] += vals_pu * g_y[cols_pu]   (out pre-set to e - x)
__global__ void scatter_phase2(const float* __restrict__ vals,
                               const int*   __restrict__ rows,
                               const int*   __restrict__ cols,
                               float*       __restrict__ out,
                               int nnz) {
    scatter_row(vals, rows, cols, g_y, out, nnz);
}

// ---------------------------------------------------------------------------
// Launch
// ---------------------------------------------------------------------------
extern "C" void kernel_launch(void* const* d_in, const int* in_sizes, int n_in,
                              void* d_out, int out_size) {
    // Inputs (metadata order): t, x, e, vals_up, vals_pu,
    //                          rows_up, cols_up, rows_pu, cols_pu
    // Handle a possibly-absent leading scalar 't'.
    const int base = n_in - 8;

    const float* x       = (const float*)d_in[base + 0];
    const float* e       = (const float*)d_in[base + 1];
    const float* vals_up = (const float*)d_in[base + 2];
    const float* vals_pu = (const float*)d_in[base + 3];
    const int*   rows_up = (const int*)  d_in[base + 4];
    const int*   cols_up = (const int*)  d_in[base + 5];
    const int*   rows_pu = (const int*)  d_in[base + 6];
    const int*   cols_pu = (const int*)  d_in[base + 7];

    float* out = (float*)d_out;

    const int threads = 256;

    // init: cover max(y float4 count, out float4 count) = 3.2M threads
    const int ny4 = (U_ROWS * DIM) / 4;
    const int init_blocks = (ny4 + threads - 1) / threads;
    init_kernel<<<init_blocks, threads>>>(x, e, out);

    // scatter: one warp per nnz → NNZ*32 threads
    const long long total_scatter = (long long)NNZ_CNT * 32;
    const int scatter_blocks = (int)((total_scatter + threads - 1) / threads);

    scatter_phase1<<<scatter_blocks, threads>>>(vals_up, rows_up, cols_up, x, NNZ_CNT);
    scatter_phase2<<<scatter_blocks, threads>>>(vals_pu, rows_pu, cols_pu, out, NNZ_CNT);
}